// round 12
// baseline (speedup 1.0000x reference)
#include <cuda_runtime.h>
#include <cuda_fp16.h>

#define TN 2048
#define RMAXF 8.0f
#define ICUT 1535            /* table index at r=6.0; g beyond is ~1e-8 */
#define MAXAB 32768
#define MAXE  640000
#define MAXP  262144
#define KSLOT 12
#define MAXOV 4096

// Radial table (fp16 lerp pairs): g16[i*48+o] = (g[i][o], g[i+1][o]),
// g[i][t*16+m] = (silu(rb(r_i)@w1[t]) @ w2[t])[m] / sqrt(20).
// g(r)==~0 for r > 5.8, so dropping r>6 edges and clamping r>RMAXF is safe.
__device__ __align__(16) __half2 g16[TN * 48];
__device__ float rb_tab[TN * 10];
__device__ float act_tab[TN * 300];
__device__ float rw_table[3 * MAXAB];   // dot(atom_rep[t][a], w_out)
__device__ __half rep16[3 * MAXAB * 128];
// per-probe fixed-slot buckets of contributing edges
__device__ float4 rec[MAXE];            // (c0,c1,c2, src-as-float)
__device__ int    slots[MAXP * KSLOT];
__device__ int    cnt[MAXP];
// overflow (beyond KSLOT per probe; probability ~1e-14 per probe)
__device__ int    ovcount;
__device__ int2   ovbuf[MAXOV];         // (dst, edge)

// ---------------- 1: radial basis table -------------------------------------
__global__ void rb_kernel()
{
    int id = blockIdx.x * blockDim.x + threadIdx.x;
    if (id >= TN * 10) return;
    int i = id / 10, k = id % 10;
    float r = (float)i * (RMAXF / (float)(TN - 1));
    const float step = 4.0f / 9.0f;
    float d = (r - (float)k * step) / step;
    rb_tab[id] = expf(-d * d) * 1.12f;
}

// ---------------- 2: hidden activations + cnt init --------------------------
__global__ void act_kernel(const float* __restrict__ w1, int P)
{
    int id = blockIdx.x * blockDim.x + threadIdx.x;
    if (id < P) cnt[id] = 0;
    if (id == 0) ovcount = 0;
    if (id >= TN * 300) return;
    int i = id / 300, rem = id % 300;
    int t = rem / 100, j = rem % 100;
    const float* RB = rb_tab + i * 10;
    const float* W1 = w1 + t * 1000 + j;
    float a = 0.f;
#pragma unroll
    for (int k = 0; k < 10; k++)
        a = fmaf(__ldg(RB + k), __ldg(W1 + k * 100), a);
    act_tab[id] = a / (1.f + expf(-a));
}

// ---------------- 3: output table, fp16 lerp pairs directly -----------------
__global__ void gtab16_kernel(const float* __restrict__ w2)
{
    int id = blockIdx.x * blockDim.x + threadIdx.x;
    if (id >= TN * 48) return;
    int i = id / 48, o = id % 48;
    int t = o >> 4, m = o & 15;
    const float* A0 = act_tab + i * 300 + t * 100;
    const float* A1 = act_tab + min(i + 1, TN - 1) * 300 + t * 100;
    const float* W = w2 + t * 1600 + m;
    float h0 = 0.f, h1 = 0.f;
#pragma unroll 4
    for (int j = 0; j < 100; j++) {
        float wv = __ldg(W + j * 16);
        h0 = fmaf(__ldg(A0 + j), wv, h0);
        h1 = fmaf(__ldg(A1 + j), wv, h1);
    }
    const float scale = 0.22360679774997896f;  // 1/sqrt(20)
    g16[id] = __floats2half2_rn(h0 * scale, h1 * scale);
}

// ---------------- 4: phase A — thread per edge, survivors only --------------
__global__ void __launch_bounds__(256) phaseA_kernel(
    const float* __restrict__ atom_xyz,
    const float* __restrict__ probe_xyz,
    const int*   __restrict__ edges,
    const float* __restrict__ ped,
    const float* __restrict__ cell,
    int E, int n_edges_b, int n_atoms, int n_probes)
{
    int e = blockIdx.x * 256 + threadIdx.x;
    if (e >= E) return;

    int b = e / n_edges_b;
    int2 se = ((const int2*)edges)[e];
    int src_g = b * n_atoms + se.x;
    int dst_g = b * n_probes + se.y;
    float px = ped[3 * e], py = ped[3 * e + 1], pz = ped[3 * e + 2];
    const float* C = cell + b * 9;
    float dx = fmaf(px, __ldg(C + 0), fmaf(py, __ldg(C + 3), pz * __ldg(C + 6)));
    float dy = fmaf(px, __ldg(C + 1), fmaf(py, __ldg(C + 4), pz * __ldg(C + 7)));
    float dz = fmaf(px, __ldg(C + 2), fmaf(py, __ldg(C + 5), pz * __ldg(C + 8)));
    float vx = probe_xyz[3 * dst_g + 0] - atom_xyz[3 * src_g + 0] - dx;
    float vy = probe_xyz[3 * dst_g + 1] - atom_xyz[3 * src_g + 1] - dy;
    float vz = probe_xyz[3 * dst_g + 2] - atom_xyz[3 * src_g + 2] - dz;
    float r2 = fmaf(vx, vx, fmaf(vy, vy, vz * vz));
    float r = sqrtf(r2);

    float f = r * ((float)(TN - 1) / RMAXF);
    int i0 = (int)f;
    if (i0 >= ICUT) return;          // g(r>6) ~ 0: drop, no further work

    float w = f - (float)i0;
    float rinv = 1.0f / fmaxf(r, 1e-9f);
    float x = vx * rinv, y = vy * rinv, z = vz * rinv;
    float x2 = x * x, y2 = y * y, z2 = z * z;

    const float s3  = 1.7320508075688772f;
    const float s15 = 3.872983346207417f;
    float sh[16];
    sh[0]  = 1.f;
    sh[1]  = s3 * x;
    sh[2]  = s3 * y;
    sh[3]  = s3 * z;
    sh[4]  = s15 * x * y;
    sh[5]  = s15 * y * z;
    sh[6]  = 1.118033988749895f * (3.f * z2 - 1.f);
    sh[7]  = s15 * x * z;
    sh[8]  = 1.9364916731037085f * (x2 - y2);
    sh[9]  = 2.091650066335189f * y * (3.f * x2 - y2);
    sh[10] = 10.246950765959598f * x * y * z;
    sh[11] = 1.6201851746019651f * y * (5.f * z2 - 1.f);
    sh[12] = 1.3228756555322954f * (5.f * z2 * z - 3.f * z);
    sh[13] = 1.6201851746019651f * x * (5.f * z2 - 1.f);
    sh[14] = 5.123475382979799f * z * (x2 - y2);
    sh[15] = 2.091650066335189f * x * (x2 - 3.f * y2);

    // table read: 12 aligned 16B loads (192 B contiguous per entry)
    const uint4* G = (const uint4*)(g16 + (size_t)i0 * 48);
    float sc[3];
#pragma unroll
    for (int t = 0; t < 3; t++) {
        float acc = 0.f;
#pragma unroll
        for (int q = 0; q < 4; q++) {
            uint4 u = __ldg(G + t * 4 + q);
            float2 p0 = __half22float2(*(__half2*)&u.x);
            float2 p1 = __half22float2(*(__half2*)&u.y);
            float2 p2 = __half22float2(*(__half2*)&u.z);
            float2 p3 = __half22float2(*(__half2*)&u.w);
            int mb = q * 4;
            acc = fmaf(sh[mb + 0], fmaf(w, p0.y - p0.x, p0.x), acc);
            acc = fmaf(sh[mb + 1], fmaf(w, p1.y - p1.x, p1.x), acc);
            acc = fmaf(sh[mb + 2], fmaf(w, p2.y - p2.x, p2.x), acc);
            acc = fmaf(sh[mb + 3], fmaf(w, p3.y - p3.x, p3.x), acc);
        }
        sc[t] = acc;
    }

    rec[e] = make_float4(sc[0], sc[1], sc[2], __int_as_float(src_g));
    int slot = atomicAdd(&cnt[dst_g], 1);
    if (slot < KSLOT) {
        slots[dst_g * KSLOT + slot] = e;
    } else {
        int j = atomicAdd(&ovcount, 1);     // ~never happens
        if (j < MAXOV) ovbuf[j] = make_int2(dst_g, e);
    }
}

// ---------------- 5: prep — rep16 convert + rw dot --------------------------
__global__ void prep_rep_kernel(const float* __restrict__ atom_rep,
                                const float* __restrict__ w_out, int rows)
{
    int g = blockIdx.x * blockDim.x + threadIdx.x;
    int row = g >> 5;
    int lane = g & 31;
    if (row >= rows) return;
    float4 a = __ldg((const float4*)atom_rep + (size_t)row * 32 + lane);
    __half2 h0 = __floats2half2_rn(a.x, a.y);
    __half2 h1 = __floats2half2_rn(a.z, a.w);
    uint2 u;
    u.x = *(unsigned*)&h0;
    u.y = *(unsigned*)&h1;
    ((uint2*)rep16)[(size_t)row * 32 + lane] = u;
    float4 wv = __ldg((const float4*)w_out + lane);
    float s = fmaf(a.x, wv.x, fmaf(a.y, wv.y, fmaf(a.z, wv.z, a.w * wv.w)));
#pragma unroll
    for (int off = 16; off > 0; off >>= 1)
        s += __shfl_xor_sync(0xFFFFFFFFu, s, off);
    if (lane == 0) rw_table[row] = s;
}

// ---------------- 6: phase B — warp per probe, fixed-depth loads ------------
__device__ __forceinline__ void accum_edge(
    int e, int lane, int AB, size_t repT2,
    float4& acc, float& ov)
{
    const __half2* rep2 = (const __half2*)rep16;
    float4 c = __ldg(&rec[e]);               // broadcast (same addr all lanes)
    int src = __float_as_int(c.w);
    const __half2* p0 = rep2 + (size_t)src * 64 + lane * 2;
    uint2 u0 = __ldg((const uint2*)p0);
    uint2 u1 = __ldg((const uint2*)(p0 + repT2));
    uint2 u2 = __ldg((const uint2*)(p0 + 2 * repT2));
    float2 a0 = __half22float2(*(__half2*)&u0.x);
    float2 b0 = __half22float2(*(__half2*)&u0.y);
    float2 a1 = __half22float2(*(__half2*)&u1.x);
    float2 b1 = __half22float2(*(__half2*)&u1.y);
    float2 a2 = __half22float2(*(__half2*)&u2.x);
    float2 b2 = __half22float2(*(__half2*)&u2.y);
    acc.x += fmaf(c.x, a0.x, fmaf(c.y, a1.x, c.z * a2.x));
    acc.y += fmaf(c.x, a0.y, fmaf(c.y, a1.y, c.z * a2.y));
    acc.z += fmaf(c.x, b0.x, fmaf(c.y, b1.x, c.z * b2.x));
    acc.w += fmaf(c.x, b0.y, fmaf(c.y, b1.y, c.z * b2.y));
    if (lane == 0)
        ov += fmaf(c.x, rw_table[src],
              fmaf(c.y, rw_table[AB + src], c.z * rw_table[2 * AB + src]));
}

__global__ void __launch_bounds__(256) phaseB_kernel(
    float* __restrict__ probes, float* __restrict__ out, int P, int AB)
{
    int g = blockIdx.x * blockDim.x + threadIdx.x;
    int p = g >> 5;
    int lane = g & 31;
    if (p >= P) return;

    float4 acc = make_float4(0.f, 0.f, 0.f, 0.f);
    float ov = 0.f;
    size_t repT2 = (size_t)AB * 64;

    int n = min(__ldg(&cnt[p]), KSLOT);
    const int* S = slots + (size_t)p * KSLOT;
    for (int i = 0; i < n; i++)
        accum_edge(__ldg(S + i), lane, AB, repT2, acc, ov);

    int ovc = min(ovcount, MAXOV);           // uniform; ~always 0
    for (int j = 0; j < ovc; j++) {
        int2 od = ovbuf[j];
        if (od.x == p)
            accum_edge(od.y, lane, AB, repT2, acc, ov);
    }

    ((float4*)(probes + (size_t)p * 128))[lane] = acc;
    if (lane == 0) out[p] = ov;
}

extern "C" void kernel_launch(void* const* d_in, const int* in_sizes, int n_in,
                              void* d_out, int out_size)
{
    const float* atom_xyz  = (const float*)d_in[0];
    const float* probe_xyz = (const float*)d_in[1];
    const int*   edges     = (const int*)d_in[2];
    const float* ped       = (const float*)d_in[3];
    const float* cell      = (const float*)d_in[4];
    const float* atom_rep  = (const float*)d_in[8];
    const float* w1        = (const float*)d_in[9];
    const float* w2        = (const float*)d_in[10];
    const float* w_out     = (const float*)d_in[11];

    int B         = in_sizes[4] / 9;
    int n_atoms   = in_sizes[0] / (3 * B);
    int n_probes  = in_sizes[1] / (3 * B);
    int n_edges_b = in_sizes[2] / (2 * B);
    int E  = B * n_edges_b;
    int AB = B * n_atoms;
    int P  = B * n_probes;

    float* out    = (float*)d_out;      // first P: (B,P) potential
    float* probes = out + P;            // next P*128: probe features

    int actN = (TN * 300 > P) ? TN * 300 : P;
    rb_kernel<<<(TN * 10 + 255) / 256, 256>>>();
    act_kernel<<<(actN + 255) / 256, 256>>>(w1, P);       // + cnt init
    gtab16_kernel<<<(TN * 48 + 255) / 256, 256>>>(w2);
    phaseA_kernel<<<(E + 255) / 256, 256>>>(atom_xyz, probe_xyz, edges, ped,
                                            cell, E, n_edges_b, n_atoms,
                                            n_probes);
    prep_rep_kernel<<<(3 * AB * 32 + 255) / 256, 256>>>(atom_rep, w_out, 3 * AB);
    phaseB_kernel<<<(P * 32 + 255) / 256, 256>>>(probes, out, P, AB);
}

// round 14
// speedup vs baseline: 1.1125x; 1.1125x over previous
#include <cuda_runtime.h>
#include <cuda_fp16.h>

#define TN 2048
#define RMAXF 8.0f
#define ICUT 1535            /* table index at r=6.0; g beyond is ~1e-8 */
#define MAXAB 32768
#define MAXE  640000
#define MAXP  262144

// Radial table (fp16 lerp pairs): g16[i*48+o] = (g[i][o], g[i+1][o]),
// g[i][t*16+m] = (silu(rb(r_i)@w1[t]) @ w2[t])[m] / sqrt(20).
// g(r)==~0 for r > 5.8, so dropping r>6 edges and clamping r>RMAXF is safe.
__device__ __align__(16) __half2 g16[TN * 48];
__device__ float rb_tab[TN * 10];
__device__ float act_tab[TN * 300];
__device__ float rw_table[3 * MAXAB];   // dot(atom_rep[t][a], w_out)
__device__ __half rep16[3 * MAXAB * 128];
// per-probe linked list of contributing edges
__device__ float4 rec[MAXE];            // (c0,c1,c2, src-as-float)
__device__ int    nxt[MAXE];
__device__ int    head[MAXP];

// ---------------- 1: radial basis table -------------------------------------
__global__ void rb_kernel()
{
    int id = blockIdx.x * blockDim.x + threadIdx.x;
    if (id >= TN * 10) return;
    int i = id / 10, k = id % 10;
    float r = (float)i * (RMAXF / (float)(TN - 1));
    const float step = 4.0f / 9.0f;
    float d = (r - (float)k * step) / step;
    rb_tab[id] = expf(-d * d) * 1.12f;
}

// ---------------- 2: hidden activations + head init -------------------------
__global__ void act_kernel(const float* __restrict__ w1, int P)
{
    int id = blockIdx.x * blockDim.x + threadIdx.x;
    if (id < P) head[id] = -1;
    if (id >= TN * 300) return;
    int i = id / 300, rem = id % 300;
    int t = rem / 100, j = rem % 100;
    const float* RB = rb_tab + i * 10;
    const float* W1 = w1 + t * 1000 + j;
    float a = 0.f;
#pragma unroll
    for (int k = 0; k < 10; k++)
        a = fmaf(__ldg(RB + k), __ldg(W1 + k * 100), a);
    act_tab[id] = a / (1.f + expf(-a));
}

// ---------------- 3: output table, fp16 lerp pairs directly -----------------
__global__ void gtab16_kernel(const float* __restrict__ w2)
{
    int id = blockIdx.x * blockDim.x + threadIdx.x;
    if (id >= TN * 48) return;
    int i = id / 48, o = id % 48;
    int t = o >> 4, m = o & 15;
    const float* A0 = act_tab + i * 300 + t * 100;
    const float* A1 = act_tab + min(i + 1, TN - 1) * 300 + t * 100;
    const float* W = w2 + t * 1600 + m;
    float h0 = 0.f, h1 = 0.f;
#pragma unroll 4
    for (int j = 0; j < 100; j++) {
        float wv = __ldg(W + j * 16);
        h0 = fmaf(__ldg(A0 + j), wv, h0);
        h1 = fmaf(__ldg(A1 + j), wv, h1);
    }
    const float scale = 0.22360679774997896f;  // 1/sqrt(20)
    g16[id] = __floats2half2_rn(h0 * scale, h1 * scale);
}

// ---------------- 4: phase A — thread per edge, survivors only --------------
__global__ void __launch_bounds__(256) phaseA_kernel(
    const float* __restrict__ atom_xyz,
    const float* __restrict__ probe_xyz,
    const int*   __restrict__ edges,
    const float* __restrict__ ped,
    const float* __restrict__ cell,
    int E, int n_edges_b, int n_atoms, int n_probes)
{
    int e = blockIdx.x * 256 + threadIdx.x;
    if (e >= E) return;

    int b = e / n_edges_b;
    int2 se = ((const int2*)edges)[e];
    int src_g = b * n_atoms + se.x;
    int dst_g = b * n_probes + se.y;
    float px = ped[3 * e], py = ped[3 * e + 1], pz = ped[3 * e + 2];
    const float* C = cell + b * 9;
    float dx = fmaf(px, __ldg(C + 0), fmaf(py, __ldg(C + 3), pz * __ldg(C + 6)));
    float dy = fmaf(px, __ldg(C + 1), fmaf(py, __ldg(C + 4), pz * __ldg(C + 7)));
    float dz = fmaf(px, __ldg(C + 2), fmaf(py, __ldg(C + 5), pz * __ldg(C + 8)));
    float vx = probe_xyz[3 * dst_g + 0] - atom_xyz[3 * src_g + 0] - dx;
    float vy = probe_xyz[3 * dst_g + 1] - atom_xyz[3 * src_g + 1] - dy;
    float vz = probe_xyz[3 * dst_g + 2] - atom_xyz[3 * src_g + 2] - dz;
    float r2 = fmaf(vx, vx, fmaf(vy, vy, vz * vz));
    float r = sqrtf(r2);

    float f = r * ((float)(TN - 1) / RMAXF);
    int i0 = (int)f;
    if (i0 >= ICUT) return;          // g(r>6) ~ 0: drop, no further work

    float w = f - (float)i0;
    float rinv = 1.0f / fmaxf(r, 1e-9f);
    float x = vx * rinv, y = vy * rinv, z = vz * rinv;
    float x2 = x * x, y2 = y * y, z2 = z * z;

    const float s3  = 1.7320508075688772f;
    const float s15 = 3.872983346207417f;
    float sh[16];
    sh[0]  = 1.f;
    sh[1]  = s3 * x;
    sh[2]  = s3 * y;
    sh[3]  = s3 * z;
    sh[4]  = s15 * x * y;
    sh[5]  = s15 * y * z;
    sh[6]  = 1.118033988749895f * (3.f * z2 - 1.f);
    sh[7]  = s15 * x * z;
    sh[8]  = 1.9364916731037085f * (x2 - y2);
    sh[9]  = 2.091650066335189f * y * (3.f * x2 - y2);
    sh[10] = 10.246950765959598f * x * y * z;
    sh[11] = 1.6201851746019651f * y * (5.f * z2 - 1.f);
    sh[12] = 1.3228756555322954f * (5.f * z2 * z - 3.f * z);
    sh[13] = 1.6201851746019651f * x * (5.f * z2 - 1.f);
    sh[14] = 5.123475382979799f * z * (x2 - y2);
    sh[15] = 2.091650066335189f * x * (x2 - 3.f * y2);

    // table read: 12 aligned 16B loads (192 B contiguous per entry)
    const uint4* G = (const uint4*)(g16 + (size_t)i0 * 48);
    float sc[3];
#pragma unroll
    for (int t = 0; t < 3; t++) {
        float acc = 0.f;
#pragma unroll
        for (int q = 0; q < 4; q++) {
            uint4 u = __ldg(G + t * 4 + q);
            float2 p0 = __half22float2(*(__half2*)&u.x);
            float2 p1 = __half22float2(*(__half2*)&u.y);
            float2 p2 = __half22float2(*(__half2*)&u.z);
            float2 p3 = __half22float2(*(__half2*)&u.w);
            int mb = q * 4;
            acc = fmaf(sh[mb + 0], fmaf(w, p0.y - p0.x, p0.x), acc);
            acc = fmaf(sh[mb + 1], fmaf(w, p1.y - p1.x, p1.x), acc);
            acc = fmaf(sh[mb + 2], fmaf(w, p2.y - p2.x, p2.x), acc);
            acc = fmaf(sh[mb + 3], fmaf(w, p3.y - p3.x, p3.x), acc);
        }
        sc[t] = acc;
    }

    rec[e] = make_float4(sc[0], sc[1], sc[2], __int_as_float(src_g));
    nxt[e] = atomicExch(&head[dst_g], e);
}

// ---------------- 5: prep — rep16 convert + rw dot --------------------------
__global__ void prep_rep_kernel(const float* __restrict__ atom_rep,
                                const float* __restrict__ w_out, int rows)
{
    int g = blockIdx.x * blockDim.x + threadIdx.x;
    int row = g >> 5;
    int lane = g & 31;
    if (row >= rows) return;
    float4 a = __ldg((const float4*)atom_rep + (size_t)row * 32 + lane);
    __half2 h0 = __floats2half2_rn(a.x, a.y);
    __half2 h1 = __floats2half2_rn(a.z, a.w);
    uint2 u;
    u.x = *(unsigned*)&h0;
    u.y = *(unsigned*)&h1;
    ((uint2*)rep16)[(size_t)row * 32 + lane] = u;
    float4 wv = __ldg((const float4*)w_out + lane);
    float s = fmaf(a.x, wv.x, fmaf(a.y, wv.y, fmaf(a.z, wv.z, a.w * wv.w)));
#pragma unroll
    for (int off = 16; off > 0; off >>= 1)
        s += __shfl_xor_sync(0xFFFFFFFFu, s, off);
    if (lane == 0) rw_table[row] = s;
}

// ---------------- 6: phase B — warp handles 4 probes (MLP across probes) ----
__global__ void __launch_bounds__(128) phaseB_kernel(
    float* __restrict__ probes, float* __restrict__ out, int P, int AB)
{
    int g = blockIdx.x * blockDim.x + threadIdx.x;
    int wrp = g >> 5;
    int lane = g & 31;
    int p0 = wrp * 4;
    if (p0 >= P) return;

    size_t repT2 = (size_t)AB * 64;
    const __half2* rep2 = (const __half2*)rep16;

    float4 acc[4];
    float ov[4];
    int e[4];
#pragma unroll
    for (int k = 0; k < 4; k++) {
        acc[k] = make_float4(0.f, 0.f, 0.f, 0.f);
        ov[k] = 0.f;
        int p = p0 + k;
        e[k] = (p < P) ? __ldg(&head[p]) : -1;   // 4 independent loads
    }

    // e[k] is warp-uniform -> divergence-free loop; typical 0-1 iterations
    while (e[0] >= 0 || e[1] >= 0 || e[2] >= 0 || e[3] >= 0) {
        float4 c[4];
#pragma unroll
        for (int k = 0; k < 4; k++)
            if (e[k] >= 0) c[k] = __ldg(&rec[e[k]]);   // independent
#pragma unroll
        for (int k = 0; k < 4; k++) {
            if (e[k] < 0) continue;
            int src = __float_as_int(c[k].w);
            const __half2* pp = rep2 + (size_t)src * 64 + lane * 2;
            uint2 u0 = __ldg((const uint2*)pp);
            uint2 u1 = __ldg((const uint2*)(pp + repT2));
            uint2 u2 = __ldg((const uint2*)(pp + 2 * repT2));
            float2 a0 = __half22float2(*(__half2*)&u0.x);
            float2 b0 = __half22float2(*(__half2*)&u0.y);
            float2 a1 = __half22float2(*(__half2*)&u1.x);
            float2 b1 = __half22float2(*(__half2*)&u1.y);
            float2 a2 = __half22float2(*(__half2*)&u2.x);
            float2 b2 = __half22float2(*(__half2*)&u2.y);
            acc[k].x += fmaf(c[k].x, a0.x, fmaf(c[k].y, a1.x, c[k].z * a2.x));
            acc[k].y += fmaf(c[k].x, a0.y, fmaf(c[k].y, a1.y, c[k].z * a2.y));
            acc[k].z += fmaf(c[k].x, b0.x, fmaf(c[k].y, b1.x, c[k].z * b2.x));
            acc[k].w += fmaf(c[k].x, b0.y, fmaf(c[k].y, b1.y, c[k].z * b2.y));
            if (lane == 0)
                ov[k] += fmaf(c[k].x, rw_table[src],
                         fmaf(c[k].y, rw_table[AB + src],
                              c[k].z * rw_table[2 * AB + src]));
            e[k] = __ldg(&nxt[e[k]]);
        }
    }

#pragma unroll
    for (int k = 0; k < 4; k++) {
        int p = p0 + k;
        if (p < P) {
            ((float4*)(probes + (size_t)p * 128))[lane] = acc[k];
            if (lane == 0) out[p] = ov[k];
        }
    }
}

extern "C" void kernel_launch(void* const* d_in, const int* in_sizes, int n_in,
                              void* d_out, int out_size)
{
    const float* atom_xyz  = (const float*)d_in[0];
    const float* probe_xyz = (const float*)d_in[1];
    const int*   edges     = (const int*)d_in[2];
    const float* ped       = (const float*)d_in[3];
    const float* cell      = (const float*)d_in[4];
    const float* atom_rep  = (const float*)d_in[8];
    const float* w1        = (const float*)d_in[9];
    const float* w2        = (const float*)d_in[10];
    const float* w_out     = (const float*)d_in[11];

    int B         = in_sizes[4] / 9;
    int n_atoms   = in_sizes[0] / (3 * B);
    int n_probes  = in_sizes[1] / (3 * B);
    int n_edges_b = in_sizes[2] / (2 * B);
    int E  = B * n_edges_b;
    int AB = B * n_atoms;
    int P  = B * n_probes;

    float* out    = (float*)d_out;      // first P: (B,P) potential
    float* probes = out + P;            // next P*128: probe features

    int actN = (TN * 300 > P) ? TN * 300 : P;
    rb_kernel<<<(TN * 10 + 255) / 256, 256>>>();
    act_kernel<<<(actN + 255) / 256, 256>>>(w1, P);       // + head init
    gtab16_kernel<<<(TN * 48 + 255) / 256, 256>>>(w2);
    phaseA_kernel<<<(E + 255) / 256, 256>>>(atom_xyz, probe_xyz, edges, ped,
                                            cell, E, n_edges_b, n_atoms,
                                            n_probes);
    prep_rep_kernel<<<(3 * AB * 32 + 255) / 256, 256>>>(atom_rep, w_out, 3 * AB);
    int nwarp = (P + 3) / 4;
    phaseB_kernel<<<(nwarp * 32 + 127) / 128, 128>>>(probes, out, P, AB);
}

// round 15
// speedup vs baseline: 1.3895x; 1.2490x over previous
#include <cuda_runtime.h>
#include <cuda_fp16.h>

#define TN 2048
#define RMAXF 8.0f
#define ICUT 1535            /* table index at r=6.0; g beyond is ~1e-8 */
#define RCUT2 36.0f
#define MAXAB 32768
#define MAXE  640000
#define MAXP  262144

// Radial table (fp16 lerp pairs): g16[i*48+o] = (g[i][o], g[i+1][o]),
// g[i][t*16+m] = (silu(rb(r_i)@w1[t]) @ w2[t])[m] / sqrt(20).
// g(r)==~0 for r > 5.8, so dropping r>6 edges is numerically free.
__device__ __align__(16) __half2 g16[TN * 48];
__device__ float rw_table[3 * MAXAB];   // dot(atom_rep[t][a], w_out)
__device__ __half rep16[3 * MAXAB * 128];
// per-probe linked list of contributing edges
__device__ float4 rec[MAXE];            // (c0,c1,c2, src-as-float)
__device__ int    nxt[MAXE];
__device__ int    head[MAXP];

// ---------------- 1: fused setup --------------------------------------------
// blocks [0, TN)                      : one radial-table entry each
// blocks [TN, TN+prepBlocks)          : rep16 convert + rw dot (8 rows/block)
// blocks [TN+prepBlocks, ...)         : head init
__global__ void __launch_bounds__(256) setup_kernel(
    const float* __restrict__ w1, const float* __restrict__ w2,
    const float* __restrict__ atom_rep, const float* __restrict__ w_out,
    int P, int AB, int prepBlocks)
{
    int bid = blockIdx.x;
    int tid = threadIdx.x;

    if (bid < TN) {
        // ---- table entry i: rb -> act(i, i+1) -> 48 lerp-pair outputs ----
        __shared__ float s_rb[2][10];
        __shared__ float s_act[2][300];
        int i = bid;
        if (tid < 20) {
            int which = tid / 10, k = tid % 10;
            int ii = min(i + which, TN - 1);
            float r = (float)ii * (RMAXF / (float)(TN - 1));
            const float step = 4.0f / 9.0f;
            float d = (r - (float)k * step) / step;
            s_rb[which][k] = expf(-d * d) * 1.12f;
        }
        __syncthreads();
        for (int idx = tid; idx < 600; idx += 256) {
            int which = idx / 300, rem = idx % 300;
            int t = rem / 100, j = rem % 100;
            const float* W1 = w1 + t * 1000 + j;
            float a = 0.f;
#pragma unroll
            for (int k = 0; k < 10; k++)
                a = fmaf(s_rb[which][k], __ldg(W1 + k * 100), a);
            s_act[which][rem] = a / (1.f + expf(-a));
        }
        __syncthreads();
        if (tid < 48) {
            int t = tid >> 4;
            const float* W = w2 + t * 1600 + (tid & 15);
            const float* A0 = s_act[0] + t * 100;
            const float* A1 = s_act[1] + t * 100;
            float h0 = 0.f, h1 = 0.f;
#pragma unroll 4
            for (int j = 0; j < 100; j++) {
                float wv = __ldg(W + j * 16);
                h0 = fmaf(A0[j], wv, h0);
                h1 = fmaf(A1[j], wv, h1);
            }
            const float scale = 0.22360679774997896f;  // 1/sqrt(20)
            g16[i * 48 + tid] = __floats2half2_rn(h0 * scale, h1 * scale);
        }
    } else if (bid < TN + prepBlocks) {
        // ---- rep16 convert + rw dot: warp per row ----
        int row = (bid - TN) * 8 + (tid >> 5);
        int lane = tid & 31;
        if (row >= 3 * AB) return;
        float4 a = __ldg((const float4*)atom_rep + (size_t)row * 32 + lane);
        __half2 h0 = __floats2half2_rn(a.x, a.y);
        __half2 h1 = __floats2half2_rn(a.z, a.w);
        uint2 u;
        u.x = *(unsigned*)&h0;
        u.y = *(unsigned*)&h1;
        ((uint2*)rep16)[(size_t)row * 32 + lane] = u;
        float4 wv = __ldg((const float4*)w_out + lane);
        float s = fmaf(a.x, wv.x, fmaf(a.y, wv.y, fmaf(a.z, wv.z, a.w * wv.w)));
#pragma unroll
        for (int off = 16; off > 0; off >>= 1)
            s += __shfl_xor_sync(0xFFFFFFFFu, s, off);
        if (lane == 0) rw_table[row] = s;
    } else {
        // ---- head init ----
        int idx = (bid - TN - prepBlocks) * 256 + tid;
        if (idx < P) head[idx] = -1;
    }
}

// ---------------- 2: phase A — thread per edge, early r^2 exit --------------
__global__ void __launch_bounds__(256) phaseA_kernel(
    const float* __restrict__ atom_xyz,
    const float* __restrict__ probe_xyz,
    const int*   __restrict__ edges,
    const float* __restrict__ ped,
    const float* __restrict__ cell,
    int E, int n_edges_b, int n_atoms, int n_probes)
{
    int e = blockIdx.x * 256 + threadIdx.x;
    if (e >= E) return;

    int b = e / n_edges_b;
    int2 se = ((const int2*)edges)[e];
    int src_g = b * n_atoms + se.x;
    int dst_g = b * n_probes + se.y;
    float px = ped[3 * e], py = ped[3 * e + 1], pz = ped[3 * e + 2];
    const float* C = cell + b * 9;
    float dx = fmaf(px, __ldg(C + 0), fmaf(py, __ldg(C + 3), pz * __ldg(C + 6)));
    float dy = fmaf(px, __ldg(C + 1), fmaf(py, __ldg(C + 4), pz * __ldg(C + 7)));
    float dz = fmaf(px, __ldg(C + 2), fmaf(py, __ldg(C + 5), pz * __ldg(C + 8)));
    float vx = probe_xyz[3 * dst_g + 0] - atom_xyz[3 * src_g + 0] - dx;
    float vy = probe_xyz[3 * dst_g + 1] - atom_xyz[3 * src_g + 1] - dy;
    float vz = probe_xyz[3 * dst_g + 2] - atom_xyz[3 * src_g + 2] - dz;
    float r2 = fmaf(vx, vx, fmaf(vy, vy, vz * vz));
    if (r2 >= RCUT2) return;         // ~85% exit here: no sqrt, no SH, no insert

    float r = sqrtf(r2);
    float f = r * ((float)(TN - 1) / RMAXF);
    int i0 = (int)f;
    if (i0 >= ICUT) return;          // matches previous edge set exactly

    float w = f - (float)i0;
    float rinv = 1.0f / fmaxf(r, 1e-9f);
    float x = vx * rinv, y = vy * rinv, z = vz * rinv;
    float x2 = x * x, y2 = y * y, z2 = z * z;

    const float s3  = 1.7320508075688772f;
    const float s15 = 3.872983346207417f;
    float sh[16];
    sh[0]  = 1.f;
    sh[1]  = s3 * x;
    sh[2]  = s3 * y;
    sh[3]  = s3 * z;
    sh[4]  = s15 * x * y;
    sh[5]  = s15 * y * z;
    sh[6]  = 1.118033988749895f * (3.f * z2 - 1.f);
    sh[7]  = s15 * x * z;
    sh[8]  = 1.9364916731037085f * (x2 - y2);
    sh[9]  = 2.091650066335189f * y * (3.f * x2 - y2);
    sh[10] = 10.246950765959598f * x * y * z;
    sh[11] = 1.6201851746019651f * y * (5.f * z2 - 1.f);
    sh[12] = 1.3228756555322954f * (5.f * z2 * z - 3.f * z);
    sh[13] = 1.6201851746019651f * x * (5.f * z2 - 1.f);
    sh[14] = 5.123475382979799f * z * (x2 - y2);
    sh[15] = 2.091650066335189f * x * (x2 - 3.f * y2);

    // table read: 12 aligned 16B loads (192 B contiguous per entry)
    const uint4* G = (const uint4*)(g16 + (size_t)i0 * 48);
    float sc[3];
#pragma unroll
    for (int t = 0; t < 3; t++) {
        float acc = 0.f;
#pragma unroll
        for (int q = 0; q < 4; q++) {
            uint4 u = __ldg(G + t * 4 + q);
            float2 p0 = __half22float2(*(__half2*)&u.x);
            float2 p1 = __half22float2(*(__half2*)&u.y);
            float2 p2 = __half22float2(*(__half2*)&u.z);
            float2 p3 = __half22float2(*(__half2*)&u.w);
            int mb = q * 4;
            acc = fmaf(sh[mb + 0], fmaf(w, p0.y - p0.x, p0.x), acc);
            acc = fmaf(sh[mb + 1], fmaf(w, p1.y - p1.x, p1.x), acc);
            acc = fmaf(sh[mb + 2], fmaf(w, p2.y - p2.x, p2.x), acc);
            acc = fmaf(sh[mb + 3], fmaf(w, p3.y - p3.x, p3.x), acc);
        }
        sc[t] = acc;
    }

    rec[e] = make_float4(sc[0], sc[1], sc[2], __int_as_float(src_g));
    nxt[e] = atomicExch(&head[dst_g], e);
}

// ---------------- 3: phase B — warp handles 4 probes -------------------------
__global__ void __launch_bounds__(128) phaseB_kernel(
    float* __restrict__ probes, float* __restrict__ out, int P, int AB)
{
    int g = blockIdx.x * blockDim.x + threadIdx.x;
    int wrp = g >> 5;
    int lane = g & 31;
    int p0 = wrp * 4;
    if (p0 >= P) return;

    size_t repT2 = (size_t)AB * 64;
    const __half2* rep2 = (const __half2*)rep16;

    float4 acc[4];
    float ov[4];
    int e[4];
#pragma unroll
    for (int k = 0; k < 4; k++) {
        acc[k] = make_float4(0.f, 0.f, 0.f, 0.f);
        ov[k] = 0.f;
        int p = p0 + k;
        e[k] = (p < P) ? __ldg(&head[p]) : -1;   // 4 independent loads
    }

    while (e[0] >= 0 || e[1] >= 0 || e[2] >= 0 || e[3] >= 0) {
        float4 c[4];
#pragma unroll
        for (int k = 0; k < 4; k++)
            if (e[k] >= 0) c[k] = __ldg(&rec[e[k]]);   // independent
#pragma unroll
        for (int k = 0; k < 4; k++) {
            if (e[k] < 0) continue;
            int src = __float_as_int(c[k].w);
            const __half2* pp = rep2 + (size_t)src * 64 + lane * 2;
            uint2 u0 = __ldg((const uint2*)pp);
            uint2 u1 = __ldg((const uint2*)(pp + repT2));
            uint2 u2 = __ldg((const uint2*)(pp + 2 * repT2));
            float2 a0 = __half22float2(*(__half2*)&u0.x);
            float2 b0 = __half22float2(*(__half2*)&u0.y);
            float2 a1 = __half22float2(*(__half2*)&u1.x);
            float2 b1 = __half22float2(*(__half2*)&u1.y);
            float2 a2 = __half22float2(*(__half2*)&u2.x);
            float2 b2 = __half22float2(*(__half2*)&u2.y);
            acc[k].x += fmaf(c[k].x, a0.x, fmaf(c[k].y, a1.x, c[k].z * a2.x));
            acc[k].y += fmaf(c[k].x, a0.y, fmaf(c[k].y, a1.y, c[k].z * a2.y));
            acc[k].z += fmaf(c[k].x, b0.x, fmaf(c[k].y, b1.x, c[k].z * b2.x));
            acc[k].w += fmaf(c[k].x, b0.y, fmaf(c[k].y, b1.y, c[k].z * b2.y));
            if (lane == 0)
                ov[k] += fmaf(c[k].x, rw_table[src],
                         fmaf(c[k].y, rw_table[AB + src],
                              c[k].z * rw_table[2 * AB + src]));
            e[k] = __ldg(&nxt[e[k]]);
        }
    }

#pragma unroll
    for (int k = 0; k < 4; k++) {
        int p = p0 + k;
        if (p < P) {
            __stcs(&((float4*)(probes + (size_t)p * 128))[lane], acc[k]);
            if (lane == 0) out[p] = ov[k];
        }
    }
}

extern "C" void kernel_launch(void* const* d_in, const int* in_sizes, int n_in,
                              void* d_out, int out_size)
{
    const float* atom_xyz  = (const float*)d_in[0];
    const float* probe_xyz = (const float*)d_in[1];
    const int*   edges     = (const int*)d_in[2];
    const float* ped       = (const float*)d_in[3];
    const float* cell      = (const float*)d_in[4];
    const float* atom_rep  = (const float*)d_in[8];
    const float* w1        = (const float*)d_in[9];
    const float* w2        = (const float*)d_in[10];
    const float* w_out     = (const float*)d_in[11];

    int B         = in_sizes[4] / 9;
    int n_atoms   = in_sizes[0] / (3 * B);
    int n_probes  = in_sizes[1] / (3 * B);
    int n_edges_b = in_sizes[2] / (2 * B);
    int E  = B * n_edges_b;
    int AB = B * n_atoms;
    int P  = B * n_probes;

    float* out    = (float*)d_out;      // first P: (B,P) potential
    float* probes = out + P;            // next P*128: probe features

    int prepBlocks = (3 * AB + 7) / 8;
    int headBlocks = (P + 255) / 256;
    setup_kernel<<<TN + prepBlocks + headBlocks, 256>>>(
        w1, w2, atom_rep, w_out, P, AB, prepBlocks);
    phaseA_kernel<<<(E + 255) / 256, 256>>>(atom_xyz, probe_xyz, edges, ped,
                                            cell, E, n_edges_b, n_atoms,
                                            n_probes);
    int nwarp = (P + 3) / 4;
    phaseB_kernel<<<(nwarp * 32 + 127) / 128, 128>>>(probes, out, P, AB);
}

// round 16
// speedup vs baseline: 1.5197x; 1.0937x over previous
#include <cuda_runtime.h>
#include <cuda_fp16.h>

#define TN 1024
#define RMAXF 8.0f
#define RCUT2 36.0f
#define MAXAB 32768
#define MAXE  640000
#define MAXP  262144

// Radial table (fp16 lerp pairs): g16[i*48+o] = (g[i][o], g[i+1][o]),
// g[i][t*16+m] = (silu(rb(r_i)@w1[t]) @ w2[t])[m] / sqrt(20).
// g(r)==~0 for r > 5.8, so dropping r>6 edges is numerically free.
__device__ __align__(16) __half2 g16[TN * 48];
__device__ float act_tab[TN * 300];
__device__ float rw_table[3 * MAXAB];   // dot(atom_rep[t][a], w_out)
__device__ __half rep16[3 * MAXAB * 128];
// per-probe linked list of contributing edges
__device__ float4 rec[MAXE];            // (c0,c1,c2, src-as-float)
__device__ int    nxt[MAXE];
__device__ int    head[MAXP];

// ---------------- 1: setup1 — act_tab + rep16/rw + head init (all flat) -----
// blocks [0, actBlocks)            : act_tab, thread per activation
// blocks [actBlocks, +prepBlocks)  : rep16 convert + rw dot (8 rows/block)
// blocks [.., +headBlocks)         : head init
__global__ void __launch_bounds__(256) setup1_kernel(
    const float* __restrict__ w1,
    const float* __restrict__ atom_rep, const float* __restrict__ w_out,
    int P, int AB, int actBlocks, int prepBlocks)
{
    int bid = blockIdx.x;
    int tid = threadIdx.x;

    if (bid < actBlocks) {
        // ids [bid*256, bid*256+255] span at most 2 distinct table indices i
        __shared__ float s_rb[2][10];
        int id0 = bid * 256;
        int i_lo = id0 / 300;
        if (tid < 20) {
            int which = tid / 10, k = tid % 10;
            int ii = min(i_lo + which, TN - 1);
            float r = (float)ii * (RMAXF / (float)(TN - 1));
            const float step = 4.0f / 9.0f;
            float d = (r - (float)k * step) / step;
            s_rb[which][k] = expf(-d * d) * 1.12f;
        }
        __syncthreads();
        int id = id0 + tid;
        if (id >= TN * 300) return;
        int i = id / 300, rem = id % 300;
        int t = rem / 100, j = rem % 100;
        const float* RB = s_rb[i - i_lo];
        const float* W1 = w1 + t * 1000 + j;
        float a = 0.f;
#pragma unroll
        for (int k = 0; k < 10; k++)
            a = fmaf(RB[k], __ldg(W1 + k * 100), a);
        act_tab[id] = a / (1.f + expf(-a));
    } else if (bid < actBlocks + prepBlocks) {
        // rep16 convert + rw dot: warp per row
        int row = (bid - actBlocks) * 8 + (tid >> 5);
        int lane = tid & 31;
        if (row >= 3 * AB) return;
        float4 a = __ldg((const float4*)atom_rep + (size_t)row * 32 + lane);
        __half2 h0 = __floats2half2_rn(a.x, a.y);
        __half2 h1 = __floats2half2_rn(a.z, a.w);
        uint2 u;
        u.x = *(unsigned*)&h0;
        u.y = *(unsigned*)&h1;
        ((uint2*)rep16)[(size_t)row * 32 + lane] = u;
        float4 wv = __ldg((const float4*)w_out + lane);
        float s = fmaf(a.x, wv.x, fmaf(a.y, wv.y, fmaf(a.z, wv.z, a.w * wv.w)));
#pragma unroll
        for (int off = 16; off > 0; off >>= 1)
            s += __shfl_xor_sync(0xFFFFFFFFu, s, off);
        if (lane == 0) rw_table[row] = s;
    } else {
        int idx = (bid - actBlocks - prepBlocks) * 256 + tid;
        if (idx < P) head[idx] = -1;
    }
}

// ---------------- 2: setup2 — output table, fp16 lerp pairs -----------------
__global__ void __launch_bounds__(256) setup2_kernel(const float* __restrict__ w2)
{
    int id = blockIdx.x * blockDim.x + threadIdx.x;
    if (id >= TN * 48) return;
    int i = id / 48, o = id % 48;
    int t = o >> 4, m = o & 15;
    const float* A0 = act_tab + i * 300 + t * 100;
    const float* A1 = act_tab + min(i + 1, TN - 1) * 300 + t * 100;
    const float* W = w2 + t * 1600 + m;
    float h0 = 0.f, h1 = 0.f;
#pragma unroll 4
    for (int j = 0; j < 100; j++) {
        float wv = __ldg(W + j * 16);
        h0 = fmaf(__ldg(A0 + j), wv, h0);
        h1 = fmaf(__ldg(A1 + j), wv, h1);
    }
    const float scale = 0.22360679774997896f;  // 1/sqrt(20)
    g16[id] = __floats2half2_rn(h0 * scale, h1 * scale);
}

// ---------------- 3: phase A — thread per edge, early r^2 exit --------------
__global__ void __launch_bounds__(256) phaseA_kernel(
    const float* __restrict__ atom_xyz,
    const float* __restrict__ probe_xyz,
    const int*   __restrict__ edges,
    const float* __restrict__ ped,
    const float* __restrict__ cell,
    int E, int n_edges_b, int n_atoms, int n_probes)
{
    int e = blockIdx.x * 256 + threadIdx.x;
    if (e >= E) return;

    int b = e / n_edges_b;
    int2 se = ((const int2*)edges)[e];
    int src_g = b * n_atoms + se.x;
    int dst_g = b * n_probes + se.y;
    float px = ped[3 * e], py = ped[3 * e + 1], pz = ped[3 * e + 2];
    const float* C = cell + b * 9;
    float dx = fmaf(px, __ldg(C + 0), fmaf(py, __ldg(C + 3), pz * __ldg(C + 6)));
    float dy = fmaf(px, __ldg(C + 1), fmaf(py, __ldg(C + 4), pz * __ldg(C + 7)));
    float dz = fmaf(px, __ldg(C + 2), fmaf(py, __ldg(C + 5), pz * __ldg(C + 8)));
    float vx = probe_xyz[3 * dst_g + 0] - atom_xyz[3 * src_g + 0] - dx;
    float vy = probe_xyz[3 * dst_g + 1] - atom_xyz[3 * src_g + 1] - dy;
    float vz = probe_xyz[3 * dst_g + 2] - atom_xyz[3 * src_g + 2] - dz;
    float r2 = fmaf(vx, vx, fmaf(vy, vy, vz * vz));
    if (r2 >= RCUT2) return;         // ~85% exit: no sqrt, no SH, no insert
                                     // survivors have r<6 -> i0 <= 767 < TN-1
    float r = sqrtf(r2);
    float f = r * ((float)(TN - 1) / RMAXF);
    int i0 = (int)f;
    float w = f - (float)i0;
    float rinv = 1.0f / fmaxf(r, 1e-9f);
    float x = vx * rinv, y = vy * rinv, z = vz * rinv;
    float x2 = x * x, y2 = y * y, z2 = z * z;

    const float s3  = 1.7320508075688772f;
    const float s15 = 3.872983346207417f;
    float sh[16];
    sh[0]  = 1.f;
    sh[1]  = s3 * x;
    sh[2]  = s3 * y;
    sh[3]  = s3 * z;
    sh[4]  = s15 * x * y;
    sh[5]  = s15 * y * z;
    sh[6]  = 1.118033988749895f * (3.f * z2 - 1.f);
    sh[7]  = s15 * x * z;
    sh[8]  = 1.9364916731037085f * (x2 - y2);
    sh[9]  = 2.091650066335189f * y * (3.f * x2 - y2);
    sh[10] = 10.246950765959598f * x * y * z;
    sh[11] = 1.6201851746019651f * y * (5.f * z2 - 1.f);
    sh[12] = 1.3228756555322954f * (5.f * z2 * z - 3.f * z);
    sh[13] = 1.6201851746019651f * x * (5.f * z2 - 1.f);
    sh[14] = 5.123475382979799f * z * (x2 - y2);
    sh[15] = 2.091650066335189f * x * (x2 - 3.f * y2);

    // table read: 12 aligned 16B loads (192 B contiguous per entry)
    const uint4* G = (const uint4*)(g16 + (size_t)i0 * 48);
    float sc[3];
#pragma unroll
    for (int t = 0; t < 3; t++) {
        float acc = 0.f;
#pragma unroll
        for (int q = 0; q < 4; q++) {
            uint4 u = __ldg(G + t * 4 + q);
            float2 p0 = __half22float2(*(__half2*)&u.x);
            float2 p1 = __half22float2(*(__half2*)&u.y);
            float2 p2 = __half22float2(*(__half2*)&u.z);
            float2 p3 = __half22float2(*(__half2*)&u.w);
            int mb = q * 4;
            acc = fmaf(sh[mb + 0], fmaf(w, p0.y - p0.x, p0.x), acc);
            acc = fmaf(sh[mb + 1], fmaf(w, p1.y - p1.x, p1.x), acc);
            acc = fmaf(sh[mb + 2], fmaf(w, p2.y - p2.x, p2.x), acc);
            acc = fmaf(sh[mb + 3], fmaf(w, p3.y - p3.x, p3.x), acc);
        }
        sc[t] = acc;
    }

    rec[e] = make_float4(sc[0], sc[1], sc[2], __int_as_float(src_g));
    nxt[e] = atomicExch(&head[dst_g], e);
}

// ---------------- 4: phase B — warp handles 4 probes -------------------------
__global__ void __launch_bounds__(128) phaseB_kernel(
    float* __restrict__ probes, float* __restrict__ out, int P, int AB)
{
    int g = blockIdx.x * blockDim.x + threadIdx.x;
    int wrp = g >> 5;
    int lane = g & 31;
    int p0 = wrp * 4;
    if (p0 >= P) return;

    size_t repT2 = (size_t)AB * 64;
    const __half2* rep2 = (const __half2*)rep16;

    float4 acc[4];
    float ov[4];
    int e[4];
#pragma unroll
    for (int k = 0; k < 4; k++) {
        acc[k] = make_float4(0.f, 0.f, 0.f, 0.f);
        ov[k] = 0.f;
        int p = p0 + k;
        e[k] = (p < P) ? __ldg(&head[p]) : -1;   // 4 independent loads
    }

    while (e[0] >= 0 || e[1] >= 0 || e[2] >= 0 || e[3] >= 0) {
        float4 c[4];
#pragma unroll
        for (int k = 0; k < 4; k++)
            if (e[k] >= 0) c[k] = __ldg(&rec[e[k]]);   // independent
#pragma unroll
        for (int k = 0; k < 4; k++) {
            if (e[k] < 0) continue;
            int src = __float_as_int(c[k].w);
            const __half2* pp = rep2 + (size_t)src * 64 + lane * 2;
            uint2 u0 = __ldg((const uint2*)pp);
            uint2 u1 = __ldg((const uint2*)(pp + repT2));
            uint2 u2 = __ldg((const uint2*)(pp + 2 * repT2));
            float2 a0 = __half22float2(*(__half2*)&u0.x);
            float2 b0 = __half22float2(*(__half2*)&u0.y);
            float2 a1 = __half22float2(*(__half2*)&u1.x);
            float2 b1 = __half22float2(*(__half2*)&u1.y);
            float2 a2 = __half22float2(*(__half2*)&u2.x);
            float2 b2 = __half22float2(*(__half2*)&u2.y);
            acc[k].x += fmaf(c[k].x, a0.x, fmaf(c[k].y, a1.x, c[k].z * a2.x));
            acc[k].y += fmaf(c[k].x, a0.y, fmaf(c[k].y, a1.y, c[k].z * a2.y));
            acc[k].z += fmaf(c[k].x, b0.x, fmaf(c[k].y, b1.x, c[k].z * b2.x));
            acc[k].w += fmaf(c[k].x, b0.y, fmaf(c[k].y, b1.y, c[k].z * b2.y));
            if (lane == 0)
                ov[k] += fmaf(c[k].x, rw_table[src],
                         fmaf(c[k].y, rw_table[AB + src],
                              c[k].z * rw_table[2 * AB + src]));
            e[k] = __ldg(&nxt[e[k]]);
        }
    }

#pragma unroll
    for (int k = 0; k < 4; k++) {
        int p = p0 + k;
        if (p < P) {
            __stcs(&((float4*)(probes + (size_t)p * 128))[lane], acc[k]);
            if (lane == 0) out[p] = ov[k];
        }
    }
}

extern "C" void kernel_launch(void* const* d_in, const int* in_sizes, int n_in,
                              void* d_out, int out_size)
{
    const float* atom_xyz  = (const float*)d_in[0];
    const float* probe_xyz = (const float*)d_in[1];
    const int*   edges     = (const int*)d_in[2];
    const float* ped       = (const float*)d_in[3];
    const float* cell      = (const float*)d_in[4];
    const float* atom_rep  = (const float*)d_in[8];
    const float* w1        = (const float*)d_in[9];
    const float* w2        = (const float*)d_in[10];
    const float* w_out     = (const float*)d_in[11];

    int B         = in_sizes[4] / 9;
    int n_atoms   = in_sizes[0] / (3 * B);
    int n_probes  = in_sizes[1] / (3 * B);
    int n_edges_b = in_sizes[2] / (2 * B);
    int E  = B * n_edges_b;
    int AB = B * n_atoms;
    int P  = B * n_probes;

    float* out    = (float*)d_out;      // first P: (B,P) potential
    float* probes = out + P;            // next P*128: probe features

    int actBlocks  = (TN * 300 + 255) / 256;
    int prepBlocks = (3 * AB + 7) / 8;
    int headBlocks = (P + 255) / 256;
    setup1_kernel<<<actBlocks + prepBlocks + headBlocks, 256>>>(
        w1, atom_rep, w_out, P, AB, actBlocks, prepBlocks);
    setup2_kernel<<<(TN * 48 + 255) / 256, 256>>>(w2);
    phaseA_kernel<<<(E + 255) / 256, 256>>>(atom_xyz, probe_xyz, edges, ped,
                                            cell, E, n_edges_b, n_atoms,
                                            n_probes);
    int nwarp = (P + 3) / 4;
    phaseB_kernel<<<(nwarp * 32 + 127) / 128, 128>>>(probes, out, P, AB);
}